// round 1
// baseline (speedup 1.0000x reference)
#include <cuda_runtime.h>
#include <stdint.h>

#define BN_EPS 1e-5f

namespace {
constexpr int Nn = 64, C = 256, H = 56, W = 56;
constexpr int HP = H + 2, WPAD = W + 2;         // zero-padded bitplane dims
constexpr int WORDS = C / 32;                    // 8 words of channel bits
constexpr int KW = 9 * WORDS;                    // 72 (tap, word) pairs
constexpr int TH = 8;                            // output rows per block
constexpr long long PIXWORDS = (long long)Nn * HP * WPAD * WORDS;
}

// Packed bitplanes (sign / nonzero) for stage inputs; padded borders stay nz=0.
__device__ uint32_t g_s1[Nn * HP * WPAD * WORDS];
__device__ uint32_t g_z1[Nn * HP * WPAD * WORDS];
__device__ uint32_t g_s2[Nn * HP * WPAD * WORDS];
__device__ uint32_t g_z2[Nn * HP * WPAD * WORDS];
__device__ uint32_t g_wb1[C * KW];
__device__ uint32_t g_wb2[C * KW];

// Zero nz planes each launch (borders must read as "no contribution";
// interiors are fully overwritten by pack / conv1 afterwards).
__global__ void k_zero_nz() {
    long long stride = (long long)gridDim.x * blockDim.x;
    for (long long i = blockIdx.x * (long long)blockDim.x + threadIdx.x;
         i < PIXWORDS; i += stride) {
        g_z1[i] = 0u;
        g_z2[i] = 0u;
    }
}

// Pack input activations: grid (H, N), block (W=56, WORDS=8).
// For fixed (wd, ci) the 56 x-threads read consecutive floats -> coalesced.
__global__ void k_pack_x(const float* __restrict__ x) {
    const int h = blockIdx.x;
    const int n = blockIdx.y;
    const int w = threadIdx.x;
    const int wd = threadIdx.y;
    const float* xp = x + (((long long)n * C + wd * 32) * H + h) * W + w;
    uint32_t s = 0, z = 0;
#pragma unroll
    for (int ci = 0; ci < 32; ci++) {
        float v = xp[(long long)ci * (H * W)];
        s |= (v > 0.f ? 1u : 0u) << ci;
        z |= (v != 0.f ? 1u : 0u) << ci;
    }
    long long idx = (((long long)n * HP + (h + 1)) * WPAD + (w + 1)) * WORDS + wd;
    g_s1[idx] = s;
    g_z1[idx] = z;
}

// Pack weights: grid (C), block (WORDS=8, 9 taps). which: 0 -> g_wb1, 1 -> g_wb2.
__global__ void k_pack_w(const float* __restrict__ w, int which) {
    uint32_t* __restrict__ outw = which ? g_wb2 : g_wb1;
    const int co = blockIdx.x;
    const int wd = threadIdx.x;
    const int tap = threadIdx.y;
    uint32_t s = 0;
#pragma unroll
    for (int ci = 0; ci < 32; ci++) {
        float v = w[(((long long)co * C) + wd * 32 + ci) * 9 + tap];
        s |= (v > 0.f ? 1u : 0u) << ci;
    }
    outw[co * KW + tap * WORDS + wd] = s;
}

// Binary conv + BN (+ residual/clip or re-binarize).
// Grid: (2 w-chunks, H/TH, N). Block: 256 threads = 8 warps.
// Warp lanes = output w (coalesced f32 I/O); warp id = output channel word.
// Inner step: 4 output channels share one x-window LDS pair -> ALU-bound.
template <int STAGE>
__global__ __launch_bounds__(256, 2) void k_bconv(
    const float* __restrict__ bn_g, const float* __restrict__ bn_b,
    const float* __restrict__ bn_m, const float* __restrict__ bn_v,
    const float* __restrict__ xres, float* __restrict__ out) {
    const uint32_t* __restrict__ sIn = (STAGE == 1) ? g_s1 : g_s2;
    const uint32_t* __restrict__ zIn = (STAGE == 1) ? g_z1 : g_z2;
    const uint32_t* __restrict__ wb = (STAGE == 1) ? g_wb1 : g_wb2;

    __shared__ uint32_t xs[WORDS * (TH + 2) * 34];
    __shared__ uint32_t xz[WORDS * (TH + 2) * 34];
    __shared__ int koff[KW];

    const int chunk = blockIdx.x;
    const int h0 = blockIdx.y * TH;
    const int n = blockIdx.z;
    const int tid = threadIdx.x;
    const int w0 = chunk * 32;

    if (tid < KW) {
        int wd = tid & 7;
        int t = tid >> 3;
        int dh = t / 3, dw = t - 3 * dh;
        koff[tid] = wd * ((TH + 2) * 34) + dh * 34 + dw;
    }

    // Load (TH+2) x 34 window of 8 sign/nz words, planar layout [wd][r][c].
    const int LW = WORDS * (TH + 2) * 34;
    for (int i = tid; i < LW; i += 256) {
        int wd = i & 7;
        int c = (i >> 3) % 34;
        int r = (i >> 3) / 34;
        int col = w0 + c;
        uint32_t s = 0, z = 0;
        if (col < WPAD) {
            long long gi = (((long long)n * HP + (h0 + r)) * WPAD + col) * WORDS + wd;
            s = sIn[gi];
            z = zIn[gi];
        }
        int si = wd * ((TH + 2) * 34) + r * 34 + c;
        xs[si] = s;
        xz[si] = z;
    }
    __syncthreads();

    const int lane = tid & 31;
    const int wid = tid >> 5;
    const int ow = w0 + lane;
    const bool act = (ow < W);

    // base[r] = sum over window of popc(nz): pixel-only term, shared by all co.
    int base[TH];
#pragma unroll
    for (int r = 0; r < TH; r++) base[r] = 0;
    for (int k = 0; k < KW; k++) {
        int off = koff[k] + lane;
#pragma unroll
        for (int r = 0; r < TH; r++) base[r] += __popc(xz[off + r * 34]);
    }

    uint32_t osig[TH], onz[TH];
    if (STAGE == 1) {
#pragma unroll
        for (int r = 0; r < TH; r++) {
            osig[r] = 0u;
            onz[r] = 0u;
        }
    }

    for (int j0 = 0; j0 < 32; j0 += 4) {
        int acc[4][TH];
#pragma unroll
        for (int jj = 0; jj < 4; jj++)
#pragma unroll
            for (int r = 0; r < TH; r++) acc[jj][r] = 0;

        const uint32_t* wp = wb + (wid * 32 + j0) * KW;
#pragma unroll 4
        for (int k = 0; k < KW; k++) {
            int off = koff[k] + lane;
            uint32_t wk0 = __ldg(wp + k);
            uint32_t wk1 = __ldg(wp + KW + k);
            uint32_t wk2 = __ldg(wp + 2 * KW + k);
            uint32_t wk3 = __ldg(wp + 3 * KW + k);
#pragma unroll
            for (int r = 0; r < TH; r++) {
                uint32_t sx = xs[off + r * 34];
                uint32_t zx = xz[off + r * 34];
                acc[0][r] += __popc(zx & (sx ^ wk0));
                acc[1][r] += __popc(zx & (sx ^ wk1));
                acc[2][r] += __popc(zx & (sx ^ wk2));
                acc[3][r] += __popc(zx & (sx ^ wk3));
            }
        }

#pragma unroll
        for (int jj = 0; jj < 4; jj++) {
            const int co = wid * 32 + j0 + jj;
            const float sc = bn_g[co] * rsqrtf(bn_v[co] + BN_EPS);
            const float sh = bn_b[co] - bn_m[co] * sc;
#pragma unroll
            for (int r = 0; r < TH; r++) {
                float t = fmaf((float)(base[r] - 2 * acc[jj][r]), sc, sh);
                if (STAGE == 1) {
                    osig[r] |= (t > 0.f ? 1u : 0u) << (j0 + jj);
                    onz[r] |= (t != 0.f ? 1u : 0u) << (j0 + jj);
                } else {
                    if (act) {
                        long long oi =
                            (((long long)n * C + co) * H + (h0 + r)) * W + ow;
                        float v = t + xres[oi];
                        v = fminf(1.f, fmaxf(-1.f, v));
                        out[oi] = v;
                    }
                }
            }
        }
    }

    if (STAGE == 1 && act) {
#pragma unroll
        for (int r = 0; r < TH; r++) {
            long long gi =
                (((long long)n * HP + (h0 + r + 1)) * WPAD + (ow + 1)) * WORDS + wid;
            g_s2[gi] = osig[r];
            g_z2[gi] = onz[r];
        }
    }
}

extern "C" void kernel_launch(void* const* d_in, const int* in_sizes, int n_in,
                              void* d_out, int out_size) {
    (void)in_sizes;
    (void)n_in;
    (void)out_size;
    const float* x = (const float*)d_in[0];
    const float* w1 = (const float*)d_in[1];
    const float* g1 = (const float*)d_in[2];
    const float* b1 = (const float*)d_in[3];
    const float* m1 = (const float*)d_in[4];
    const float* v1 = (const float*)d_in[5];
    const float* w2 = (const float*)d_in[6];
    const float* g2 = (const float*)d_in[7];
    const float* b2 = (const float*)d_in[8];
    const float* m2 = (const float*)d_in[9];
    const float* v2 = (const float*)d_in[10];
    float* out = (float*)d_out;

    k_zero_nz<<<1024, 256>>>();
    k_pack_x<<<dim3(H, Nn), dim3(W, WORDS)>>>(x);
    k_pack_w<<<C, dim3(WORDS, 9)>>>(w1, 0);
    k_pack_w<<<C, dim3(WORDS, 9)>>>(w2, 1);

    dim3 grid(2, H / TH, Nn);
    k_bconv<1><<<grid, 256>>>(g1, b1, m1, v1, x, out);
    k_bconv<2><<<grid, 256>>>(g2, b2, m2, v2, x, out);
}